// round 2
// baseline (speedup 1.0000x reference)
#include <cuda_runtime.h>
#include <cuda_bf16.h>
#include <cstdint>
#include <cstddef>

// ---------------- problem constants ----------------
#define NSAMP 2
#define CCH   256
#define VOX   32768         // 32*32*32
#define OQKV  768
#define OKV   512
#define PPOOL 512           // 8*8*8 pooled voxels
#define NHEAD 4
#define HEADD 64

// ---------------- scratch (device globals; allocation-free) ----------------
__device__ float  d_W1[NSAMP * OQKV * CCH];            // folded qkv weights
__device__ float  d_B1[NSAMP * OQKV];
__device__ float  d_W3[NSAMP * OKV * CCH];             // folded kv weights
__device__ float  d_B3[NSAMP * OKV];
__device__ float  d_qkv[(size_t)NSAMP * OQKV * VOX];   // 201 MB
__device__ float  d_y[(size_t)NSAMP * CCH * VOX];      // x + local attn (67 MB)
__device__ float  d_attnx[(size_t)NSAMP * CCH * VOX];  // groupnormed (67 MB)
__device__ float  d_pooled[NSAMP * CCH * PPOOL];       // 1 MB
__device__ float  d_kv2[NSAMP * OKV * PPOOL];          // 2 MB
__device__ float  d_q2[(size_t)NSAMP * CCH * VOX];     // 67 MB (already /16)
__device__ float  d_S[(size_t)NSAMP * NHEAD * PPOOL * VOX];   // 537 MB, layout [z][p][v]
__device__ float  d_sst[NSAMP * NHEAD * 2 * VOX];      // per-column max & 1/sum
__device__ float  d_g[(size_t)NSAMP * CCH * VOX];      // 67 MB
__device__ double d_part[1024];                        // reduction partials
__device__ float  d_stats1[4], d_stats2[4], d_stats3[4]; // (mean, rstd) per sample

// ---------------- two-stage deterministic groupnorm stats ----------------
__global__ void redsum_k(const float* __restrict__ src, long perSample,
                         int blocksPer, double* __restrict__ part) {
    int n = blockIdx.y, b = blockIdx.x, tid = threadIdx.x;
    long chunk = (perSample + blocksPer - 1) / blocksPer;
    long s0 = (long)b * chunk;
    long s1 = s0 + chunk; if (s1 > perSample) s1 = perSample;
    const float* p = src + (size_t)n * perSample;
    double s = 0.0, ss = 0.0;
    for (long i = s0 + tid; i < s1; i += blockDim.x) {
        double v = (double)p[i]; s += v; ss += v * v;
    }
    __shared__ double sh[256], sh2[256];
    sh[tid] = s; sh2[tid] = ss; __syncthreads();
    for (int o = 128; o > 0; o >>= 1) {
        if (tid < o) { sh[tid] += sh[tid + o]; sh2[tid] += sh2[tid + o]; }
        __syncthreads();
    }
    if (tid == 0) {
        part[(size_t)(n * blocksPer + b) * 2 + 0] = sh[0];
        part[(size_t)(n * blocksPer + b) * 2 + 1] = sh2[0];
    }
}

__global__ void redfin_k(const double* __restrict__ part, int blocksPer,
                         long cnt, float* __restrict__ stats) {
    int n = blockIdx.x, tid = threadIdx.x;
    double s = 0.0, ss = 0.0;
    for (int i = tid; i < blocksPer; i += blockDim.x) {
        s  += part[(size_t)(n * blocksPer + i) * 2 + 0];
        ss += part[(size_t)(n * blocksPer + i) * 2 + 1];
    }
    __shared__ double sh[256], sh2[256];
    sh[tid] = s; sh2[tid] = ss; __syncthreads();
    for (int o = 128; o > 0; o >>= 1) {
        if (tid < o) { sh[tid] += sh[tid + o]; sh2[tid] += sh2[tid + o]; }
        __syncthreads();
    }
    if (tid == 0) {
        double mean = sh[0] / (double)cnt;
        double var  = sh2[0] / (double)cnt - mean * mean;
        stats[n * 2 + 0] = (float)mean;
        stats[n * 2 + 1] = (float)(1.0 / sqrt(var + 1e-6));
    }
}

// ---------------- fold groupnorm into conv weights ----------------
__global__ void buildW_k(const float* __restrict__ W, const float* __restrict__ nw,
                         const float* __restrict__ stats, float* __restrict__ Wout, int O) {
    int idx = blockIdx.x * 256 + threadIdx.x;
    if (idx >= NSAMP * O * CCH) return;
    int c = idx & 255;
    int o = (idx >> 8) % O;
    int n = idx / (O * CCH);
    Wout[idx] = stats[n * 2 + 1] * nw[c] * W[o * CCH + c];
}

__global__ void buildB_k(const float* __restrict__ W, const float* __restrict__ nw,
                         const float* __restrict__ nb, const float* __restrict__ bias,
                         const float* __restrict__ stats, float* __restrict__ Bout, int O) {
    int idx = blockIdx.x * blockDim.x + threadIdx.x;
    if (idx >= NSAMP * O) return;
    int o = idx % O, n = idx / O;
    float mean = stats[n * 2], r = stats[n * 2 + 1];
    float s = bias[o];
    for (int c = 0; c < CCH; c++)
        s += (nb[c] - mean * r * nw[c]) * W[o * CCH + c];
    Bout[idx] = s;
}

// ---------------- generic batched SGEMM ----------------
// C[m][n] = alpha * (sum_k A*B + bias[m]) + res[m][n]
// AMODE 0: A row-major [M][K] (lda=K-ish);  AMODE 1: A [K][M] (lda = row stride)
// B always [K][N] row-major. Optional SOFTB: B' = exp(B - mx[n]) * isum[n].
#define BKK 8
template<int BM, int BN, int TM, int TN, int AMODE, int HAS_BIAS, int HAS_RES, int SOFTB>
__global__ void __launch_bounds__(256) sgemm_k(
    const float* __restrict__ A, long aZn, long aZh, int lda,
    const float* __restrict__ B, long bZn, long bZh, int ldb,
    float* __restrict__ C, long cZn, long cZh, int ldc,
    int K, int zH,
    const float* __restrict__ bias, long biasZn,
    const float* __restrict__ res, long rZn, long rZh,
    const float* __restrict__ sst, long sZn, long sZh,
    float alpha)
{
    int z = blockIdx.z;
    int zn = z / zH, zh = z - zn * zH;
    A += (size_t)zn * aZn + (size_t)zh * aZh;
    B += (size_t)zn * bZn + (size_t)zh * bZh;
    C += (size_t)zn * cZn + (size_t)zh * cZh;
    const float* mx = nullptr; const float* isum = nullptr;
    if (SOFTB) {
        const float* sb = sst + (size_t)zn * sZn + (size_t)zh * sZh;
        mx = sb; isum = sb + VOX;
    }
    if (HAS_BIAS) bias += (size_t)zn * biasZn;
    if (HAS_RES)  res  += (size_t)zn * rZn + (size_t)zh * rZh;

    int m0 = blockIdx.y * BM;
    int n0 = blockIdx.x * BN;

    __shared__ __align__(16) float As[BKK][BM + 4];
    __shared__ __align__(16) float Bs[BKK][BN];

    int tid = threadIdx.x;
    int tx = tid & ((BN / TN) - 1);       // BN/TN == 16
    int ty = tid >> 4;

    float acc[TM][TN];
    #pragma unroll
    for (int i = 0; i < TM; i++)
        #pragma unroll
        for (int j = 0; j < TN; j++) acc[i][j] = 0.f;

    for (int k0 = 0; k0 < K; k0 += BKK) {
        #pragma unroll
        for (int i = 0; i < (BM * BKK) / 256; i++) {
            int idx = i * 256 + tid;
            if (AMODE == 0) {
                int m = idx / BKK, kk = idx % BKK;
                As[kk][m] = A[(size_t)(m0 + m) * lda + (k0 + kk)];
            } else {
                int kk = idx / BM, m = idx % BM;
                As[kk][m] = A[(size_t)(k0 + kk) * lda + (m0 + m)];
            }
        }
        #pragma unroll
        for (int i = 0; i < (BN * BKK) / 256; i++) {
            int idx = i * 256 + tid;
            int kk = idx / BN, n = idx % BN;
            float v = B[(size_t)(k0 + kk) * ldb + (n0 + n)];
            if (SOFTB) v = __expf(v - mx[n0 + n]) * isum[n0 + n];
            Bs[kk][n] = v;
        }
        __syncthreads();
        #pragma unroll
        for (int kk = 0; kk < BKK; kk++) {
            float a[TM], b[TN];
            #pragma unroll
            for (int i = 0; i < TM; i += 4) {
                float4 t = *(const float4*)&As[kk][ty * TM + i];
                a[i] = t.x; a[i+1] = t.y; a[i+2] = t.z; a[i+3] = t.w;
            }
            #pragma unroll
            for (int j = 0; j < TN; j += 4) {
                float4 t = *(const float4*)&Bs[kk][tx * TN + j];
                b[j] = t.x; b[j+1] = t.y; b[j+2] = t.z; b[j+3] = t.w;
            }
            #pragma unroll
            for (int i = 0; i < TM; i++)
                #pragma unroll
                for (int j = 0; j < TN; j++)
                    acc[i][j] += a[i] * b[j];
        }
        __syncthreads();
    }

    #pragma unroll
    for (int i = 0; i < TM; i++) {
        int m = m0 + ty * TM + i;
        float bv = HAS_BIAS ? bias[m] : 0.f;
        #pragma unroll
        for (int j = 0; j < TN; j += 4) {
            int n = n0 + tx * TN + j;
            float4 o;
            o.x = alpha * (acc[i][j+0] + bv);
            o.y = alpha * (acc[i][j+1] + bv);
            o.z = alpha * (acc[i][j+2] + bv);
            o.w = alpha * (acc[i][j+3] + bv);
            if (HAS_RES) {
                float4 r = *(const float4*)&res[(size_t)m * ldc + n];
                o.x += r.x; o.y += r.y; o.z += r.z; o.w += r.w;
            }
            *(float4*)&C[(size_t)m * ldc + n] = o;
        }
    }
}

// ---------------- local windowed attention (64 tokens, 64 dims) ----------------
__global__ void __launch_bounds__(64) local_attn_k(
    const float* __restrict__ qkv, const float* __restrict__ x, float* __restrict__ y)
{
    int w = blockIdx.x;                 // 0..511 window
    int h = blockIdx.y, n = blockIdx.z;
    int gh = w >> 6, gw = (w >> 3) & 7, gd = w & 7;
    int vbase = gh * 4 * 1024 + gw * 4 * 32 + gd * 4;
    int tid = threadIdx.x;
    int a = tid >> 4, b = (tid >> 2) & 3, c = tid & 3;
    int voff = vbase + a * 1024 + b * 32 + c;

    const float* qb = qkv + ((size_t)n * OQKV + h * HEADD) * VOX;
    const float* kb = qb + (size_t)CCH * VOX;
    const float* vb = qb + (size_t)2 * CCH * VOX;

    __shared__ __align__(16) float kv_sm[64][68];
    __shared__ __align__(16) float qp[64][64];
    const float inv16 = 1.0f / 16.0f;

    for (int i = 0; i < 64; i++) {
        qp[i][tid]    = qb[(size_t)i * VOX + voff] * inv16;   // [d][tok]
        kv_sm[i][tid] = kb[(size_t)i * VOX + voff];           // K: [d][tok]
    }
    __syncthreads();

    float s[64];
    #pragma unroll
    for (int j = 0; j < 64; j++) s[j] = 0.f;
    for (int d = 0; d < 64; d++) {
        float qv = qp[d][tid];
        #pragma unroll
        for (int j4 = 0; j4 < 64; j4 += 4) {
            float4 kk = *(const float4*)&kv_sm[d][j4];
            s[j4+0] += qv * kk.x; s[j4+1] += qv * kk.y;
            s[j4+2] += qv * kk.z; s[j4+3] += qv * kk.w;
        }
    }
    float m = s[0];
    #pragma unroll
    for (int j = 1; j < 64; j++) m = fmaxf(m, s[j]);
    float sum = 0.f;
    #pragma unroll
    for (int j = 0; j < 64; j++) { s[j] = __expf(s[j] - m); sum += s[j]; }
    float inv = 1.0f / sum;
    __syncthreads();                    // all reads of qp / kv_sm done

    #pragma unroll
    for (int j = 0; j < 64; j++) qp[j][tid] = s[j] * inv;     // P: [tok j][query tid]
    for (int i = 0; i < 64; i++)
        kv_sm[tid][i] = vb[(size_t)i * VOX + voff];           // V: [tok][d]
    __syncthreads();

    float out[64];
    #pragma unroll
    for (int d = 0; d < 64; d++) out[d] = 0.f;
    for (int j = 0; j < 64; j++) {
        float pv = qp[j][tid];
        #pragma unroll
        for (int d4 = 0; d4 < 64; d4 += 4) {
            float4 vv = *(const float4*)&kv_sm[j][d4];
            out[d4+0] += pv * vv.x; out[d4+1] += pv * vv.y;
            out[d4+2] += pv * vv.z; out[d4+3] += pv * vv.w;
        }
    }
    const float* xb = x + ((size_t)n * CCH + h * HEADD) * VOX;
    float*       yb = y + ((size_t)n * CCH + h * HEADD) * VOX;
    for (int d = 0; d < 64; d++) {
        size_t idx = (size_t)d * VOX + voff;
        yb[idx] = xb[idx] + out[d];
    }
}

// ---------------- apply groupnorm elementwise (float4) ----------------
__global__ void gn_apply_k(const float* __restrict__ y, const float* __restrict__ stats,
                           const float* __restrict__ wgt, const float* __restrict__ bias,
                           float* __restrict__ out) {
    size_t idx = ((size_t)blockIdx.x * 256 + threadIdx.x) * 4;
    int c = (int)((idx >> 15) & 255);
    int n = (int)(idx >> 23);
    float mean = stats[n * 2], r = stats[n * 2 + 1];
    float w = wgt[c] * r;
    float b = bias[c] - mean * w;
    float4 v = *(const float4*)(y + idx);
    v.x = v.x * w + b; v.y = v.y * w + b; v.z = v.z * w + b; v.w = v.w * w + b;
    *(float4*)(out + idx) = v;
}

// ---------------- 4x4x4 average pool ----------------
__global__ void pool_k(const float* __restrict__ ax, float* __restrict__ pooled) {
    int idx = blockIdx.x * 256 + threadIdx.x;      // 0 .. 262143
    int pp = idx & 511;
    int c  = (idx >> 9) & 255;
    int n  = idx >> 17;
    int ph = pp >> 6, pw = (pp >> 3) & 7, pd = pp & 7;
    const float* b = ax + ((size_t)n * CCH + c) * VOX + ph * 4 * 1024 + pw * 4 * 32 + pd * 4;
    float s = 0.f;
    #pragma unroll
    for (int a = 0; a < 4; a++)
        #pragma unroll
        for (int bb = 0; bb < 4; bb++) {
            float4 v = *(const float4*)&b[a * 1024 + bb * 32];
            s += v.x + v.y + v.z + v.w;
        }
    pooled[idx] = s * (1.0f / 64.0f);
}

// ---------------- column softmax stats over S[p][v] ----------------
__global__ void softstats_k(const float* __restrict__ S, float* __restrict__ sst) {
    int v = blockIdx.x * 256 + threadIdx.x;
    int z = blockIdx.y;
    const float* col = S + (size_t)z * PPOOL * VOX + v;
    float m = -1e30f, s = 0.f;
    for (int p = 0; p < PPOOL; p++) {
        float val = col[(size_t)p * VOX];
        if (val > m) { s = s * __expf(m - val) + 1.f; m = val; }
        else         { s += __expf(val - m); }
    }
    float* o = sst + (size_t)z * 2 * VOX;
    o[v] = m; o[VOX + v] = 1.0f / s;
}

// ---------------- launch ----------------
extern "C" void kernel_launch(void* const* d_in, const int* in_sizes, int n_in,
                              void* d_out, int out_size) {
    const float* x       = (const float*)d_in[0];
    const float* qkv_w   = (const float*)d_in[1];
    const float* qkv_b   = (const float*)d_in[2];
    const float* norm_w  = (const float*)d_in[3];
    const float* norm_b  = (const float*)d_in[4];
    const float* anw     = (const float*)d_in[5];
    const float* anb     = (const float*)d_in[6];
    const float* dsw     = (const float*)d_in[7];
    const float* dsb     = (const float*)d_in[8];
    const float* q_w     = (const float*)d_in[9];
    const float* q_b     = (const float*)d_in[10];
    const float* kv_w    = (const float*)d_in[11];
    const float* kv_b    = (const float*)d_in[12];
    const float* proj_w  = (const float*)d_in[13];
    const float* proj_b  = (const float*)d_in[14];
    float* out = (float*)d_out;

    float *W1, *B1, *W3, *B3, *qkv, *y, *attnx, *pooled, *kv2, *q2, *S, *sst, *g;
    float *st1, *st2, *st3;
    double* part;
    cudaGetSymbolAddress((void**)&W1, d_W1);
    cudaGetSymbolAddress((void**)&B1, d_B1);
    cudaGetSymbolAddress((void**)&W3, d_W3);
    cudaGetSymbolAddress((void**)&B3, d_B3);
    cudaGetSymbolAddress((void**)&qkv, d_qkv);
    cudaGetSymbolAddress((void**)&y, d_y);
    cudaGetSymbolAddress((void**)&attnx, d_attnx);
    cudaGetSymbolAddress((void**)&pooled, d_pooled);
    cudaGetSymbolAddress((void**)&kv2, d_kv2);
    cudaGetSymbolAddress((void**)&q2, d_q2);
    cudaGetSymbolAddress((void**)&S, d_S);
    cudaGetSymbolAddress((void**)&sst, d_sst);
    cudaGetSymbolAddress((void**)&g, d_g);
    cudaGetSymbolAddress((void**)&part, d_part);
    cudaGetSymbolAddress((void**)&st1, d_stats1);
    cudaGetSymbolAddress((void**)&st2, d_stats2);
    cudaGetSymbolAddress((void**)&st3, d_stats3);

    const long CV = (long)CCH * VOX;        // 8388608

    // 1) stats over x, fold into qkv conv
    redsum_k<<<dim3(256, NSAMP), 256>>>(x, CV, 256, part);
    redfin_k<<<NSAMP, 256>>>(part, 256, CV, st1);
    buildW_k<<<(NSAMP * OQKV * CCH + 255) / 256, 256>>>(qkv_w, norm_w, st1, W1, OQKV);
    buildB_k<<<(NSAMP * OQKV + 255) / 256, 256>>>(qkv_w, norm_w, norm_b, qkv_b, st1, B1, OQKV);

    // 2) qkv = W1 @ x + B1   (M=768, N=32768, K=256, z=2)
    sgemm_k<128,128,8,8, 0,1,0,0><<<dim3(VOX/128, OQKV/128, NSAMP), 256>>>(
        W1, (long)OQKV*CCH, 0, CCH,  x, CV, 0, VOX,
        qkv, (long)OQKV*VOX, 0, VOX, CCH, 1,
        B1, OQKV, nullptr, 0, 0, nullptr, 0, 0, 1.0f);

    // 3) local attention -> y = x + attn
    local_attn_k<<<dim3(512, NHEAD, NSAMP), 64>>>(qkv, x, y);

    // 4) attn groupnorm
    redsum_k<<<dim3(256, NSAMP), 256>>>(y, CV, 256, part);
    redfin_k<<<NSAMP, 256>>>(part, 256, CV, st2);
    gn_apply_k<<<(int)(NSAMP * CV / 4 / 256), 256>>>(y, st2, anw, anb, attnx);

    // 5) pool + ds groupnorm folded into kv conv
    pool_k<<<NSAMP * CCH * PPOOL / 256, 256>>>(attnx, pooled);
    redsum_k<<<dim3(8, NSAMP), 256>>>(pooled, (long)CCH * PPOOL, 8, part);
    redfin_k<<<NSAMP, 256>>>(part, 8, (long)CCH * PPOOL, st3);
    buildW_k<<<(NSAMP * OKV * CCH + 255) / 256, 256>>>(kv_w, dsw, st3, W3, OKV);
    buildB_k<<<(NSAMP * OKV + 255) / 256, 256>>>(kv_w, dsw, dsb, kv_b, st3, B3, OKV);

    // 6) kv2 = W3 @ pooled + B3   (M=512, N=512, K=256, z=2)
    sgemm_k<128,128,8,8, 0,1,0,0><<<dim3(PPOOL/128, OKV/128, NSAMP), 256>>>(
        W3, (long)OKV*CCH, 0, CCH,  pooled, (long)CCH*PPOOL, 0, PPOOL,
        kv2, (long)OKV*PPOOL, 0, PPOOL, CCH, 1,
        B3, OKV, nullptr, 0, 0, nullptr, 0, 0, 1.0f);

    // 7) q2 = (q_w @ attnx + q_b) / 16   (M=256, N=32768, K=256, z=2)
    sgemm_k<128,128,8,8, 0,1,0,0><<<dim3(VOX/128, CCH/128, NSAMP), 256>>>(
        q_w, 0, 0, CCH,  attnx, CV, 0, VOX,
        q2, CV, 0, VOX, CCH, 1,
        q_b, 0, nullptr, 0, 0, nullptr, 0, 0, 1.0f/16.0f);

    // 8) S[p][v] = k2^T-style GEMM  (M=512, N=32768, K=64, z=8 (n,h))
    sgemm_k<128,128,8,8, 1,0,0,0><<<dim3(VOX/128, PPOOL/128, NSAMP*NHEAD), 256>>>(
        kv2, (long)OKV*PPOOL, (long)HEADD*PPOOL, PPOOL,
        q2, CV, (long)HEADD*VOX, VOX,
        S, (long)NHEAD*PPOOL*VOX, (long)PPOOL*VOX, VOX,
        HEADD, NHEAD,
        nullptr, 0, nullptr, 0, 0, nullptr, 0, 0, 1.0f);

    // 9) softmax stats per column
    softstats_k<<<dim3(VOX/256, NSAMP*NHEAD), 256>>>(S, sst);

    // 10) g = v2 @ softmax(S) + attnx   (M=64, N=32768, K=512, z=8)
    sgemm_k<64,128,4,8, 0,0,1,1><<<dim3(VOX/128, 1, NSAMP*NHEAD), 256>>>(
        kv2 + CCH * PPOOL, (long)OKV*PPOOL, (long)HEADD*PPOOL, PPOOL,
        S, (long)NHEAD*PPOOL*VOX, (long)PPOOL*VOX, VOX,
        g, CV, (long)HEADD*VOX, VOX,
        PPOOL, NHEAD,
        nullptr, 0,
        attnx, CV, (long)HEADD*VOX,
        sst, (long)NHEAD*2*VOX, (long)2*VOX, 1.0f);

    // 11) out = proj_w @ g + proj_b   (M=256, N=32768, K=256, z=2)
    sgemm_k<128,128,8,8, 0,1,0,0><<<dim3(VOX/128, CCH/128, NSAMP), 256>>>(
        proj_w, 0, 0, CCH,  g, CV, 0, VOX,
        out, CV, 0, VOX, CCH, 1,
        proj_b, 0, nullptr, 0, 0, nullptr, 0, 0, 1.0f);
}

// round 3
// speedup vs baseline: 2.5409x; 2.5409x over previous
#include <cuda_runtime.h>
#include <cuda_bf16.h>
#include <cstdint>
#include <cstddef>

// ---------------- problem constants ----------------
#define NSAMP 2
#define CCH   256
#define VOX   32768         // 32*32*32
#define OQKV  768
#define OKV   512
#define PPOOL 512           // 8*8*8 pooled voxels
#define NHEAD 4
#define HEADD 64

// ---------------- scratch (device globals; allocation-free) ----------------
__device__ float  d_W1[NSAMP * OQKV * CCH];
__device__ float  d_B1[NSAMP * OQKV];
__device__ float  d_W3[NSAMP * OKV * CCH];
__device__ float  d_B3[NSAMP * OKV];
__device__ float  d_qkv[(size_t)NSAMP * OQKV * VOX];   // 201 MB
__device__ float  d_y[(size_t)NSAMP * CCH * VOX];      // x + local attn
__device__ float  d_attnx[(size_t)NSAMP * CCH * VOX];
__device__ float  d_pooled[NSAMP * CCH * PPOOL];
__device__ float  d_kv2[NSAMP * OKV * PPOOL];
__device__ float  d_q2[(size_t)NSAMP * CCH * VOX];
__device__ float  d_S[(size_t)NSAMP * NHEAD * PPOOL * VOX];   // 537 MB [z][p][v]
__device__ float  d_sst[NSAMP * NHEAD * 2 * VOX];
__device__ float  d_g[(size_t)NSAMP * CCH * VOX];
__device__ double d_part[1024];
__device__ float  d_stats1[4], d_stats2[4], d_stats3[4];

// ---------------- helpers ----------------
__device__ __forceinline__ uint32_t f2tf(float x) {
    uint32_t r; asm("cvt.rna.tf32.f32 %0, %1;" : "=r"(r) : "f"(x)); return r;
}
__device__ __forceinline__ void mma8(float* c, const uint32_t* a, const uint32_t* b) {
    asm volatile(
        "mma.sync.aligned.m16n8k8.row.col.f32.tf32.tf32.f32 "
        "{%0,%1,%2,%3},{%4,%5,%6,%7},{%8,%9},{%0,%1,%2,%3};"
        : "+f"(c[0]), "+f"(c[1]), "+f"(c[2]), "+f"(c[3])
        : "r"(a[0]), "r"(a[1]), "r"(a[2]), "r"(a[3]), "r"(b[0]), "r"(b[1]));
}

// ---------------- two-stage deterministic groupnorm stats ----------------
__global__ void redsum_k(const float* __restrict__ src, long perSample,
                         int blocksPer, double* __restrict__ part) {
    int n = blockIdx.y, b = blockIdx.x, tid = threadIdx.x;
    long chunk = (perSample + blocksPer - 1) / blocksPer;
    long s0 = (long)b * chunk;
    long s1 = s0 + chunk; if (s1 > perSample) s1 = perSample;
    const float* p = src + (size_t)n * perSample;
    double s = 0.0, ss = 0.0;
    for (long i = s0 + tid; i < s1; i += blockDim.x) {
        double v = (double)p[i]; s += v; ss += v * v;
    }
    __shared__ double sh[256], sh2[256];
    sh[tid] = s; sh2[tid] = ss; __syncthreads();
    for (int o = 128; o > 0; o >>= 1) {
        if (tid < o) { sh[tid] += sh[tid + o]; sh2[tid] += sh2[tid + o]; }
        __syncthreads();
    }
    if (tid == 0) {
        part[(size_t)(n * blocksPer + b) * 2 + 0] = sh[0];
        part[(size_t)(n * blocksPer + b) * 2 + 1] = sh2[0];
    }
}

__global__ void redfin_k(const double* __restrict__ part, int blocksPer,
                         long cnt, float* __restrict__ stats) {
    int n = blockIdx.x, tid = threadIdx.x;
    double s = 0.0, ss = 0.0;
    for (int i = tid; i < blocksPer; i += blockDim.x) {
        s  += part[(size_t)(n * blocksPer + i) * 2 + 0];
        ss += part[(size_t)(n * blocksPer + i) * 2 + 1];
    }
    __shared__ double sh[256], sh2[256];
    sh[tid] = s; sh2[tid] = ss; __syncthreads();
    for (int o = 128; o > 0; o >>= 1) {
        if (tid < o) { sh[tid] += sh[tid + o]; sh2[tid] += sh2[tid + o]; }
        __syncthreads();
    }
    if (tid == 0) {
        double mean = sh[0] / (double)cnt;
        double var  = sh2[0] / (double)cnt - mean * mean;
        stats[n * 2 + 0] = (float)mean;
        stats[n * 2 + 1] = (float)(1.0 / sqrt(var + 1e-6));
    }
}

// ---------------- fold groupnorm into conv weights ----------------
__global__ void buildW_k(const float* __restrict__ W, const float* __restrict__ nw,
                         const float* __restrict__ stats, float* __restrict__ Wout, int O) {
    int idx = blockIdx.x * 256 + threadIdx.x;
    if (idx >= NSAMP * O * CCH) return;
    int c = idx & 255;
    int o = (idx >> 8) % O;
    int n = idx / (O * CCH);
    Wout[idx] = stats[n * 2 + 1] * nw[c] * W[o * CCH + c];
}

// warp per output
__global__ void buildB_k(const float* __restrict__ W, const float* __restrict__ nw,
                         const float* __restrict__ nb, const float* __restrict__ bias,
                         const float* __restrict__ stats, float* __restrict__ Bout, int O) {
    int gt = blockIdx.x * blockDim.x + threadIdx.x;
    int w = gt >> 5, lane = gt & 31;
    if (w >= NSAMP * O) return;
    int o = w % O, n = w / O;
    float mean = stats[n * 2], r = stats[n * 2 + 1];
    float s = 0.f;
    for (int c = lane; c < CCH; c += 32)
        s += (nb[c] - mean * r * nw[c]) * W[o * CCH + c];
    #pragma unroll
    for (int off = 16; off > 0; off >>= 1)
        s += __shfl_down_sync(0xffffffffu, s, off);
    if (lane == 0) Bout[w] = s + bias[o];
}

// ---------------- batched tf32 tensor-core GEMM ----------------
// C[m][n] = alpha * (sum_k A*B + bias[m]) + res[m][n]
// ALAYOUT 0: A global row-major [M][K];  ALAYOUT 1: A global [K][M].
// B always [K][N] row-major. SOFTB: B' = exp(B - mx[n]) * isum[n].
// grid: (M/BM, N/BN, Z). 256 threads = 8 warps, warp grid WM x WN.
template<int BM, int BN, int WM, int WN, int ALAYOUT, int HAS_BIAS, int HAS_RES, int SOFTB>
__global__ void __launch_bounds__(256) tgemm_k(
    const float* __restrict__ A, long aZn, long aZh, int lda,
    const float* __restrict__ B, long bZn, long bZh, int ldb,
    float* __restrict__ C, long cZn, long cZh, int ldc,
    int K, int zH,
    const float* __restrict__ bias, long biasZn,
    const float* __restrict__ res, long rZn, long rZh,
    const float* __restrict__ sst, long sZn, long sZh,
    float alpha)
{
    constexpr int BK   = 16;
    constexpr int WTM  = BM / WM;        // 64
    constexpr int WTN  = BN / WN;        // 32 or 16
    constexpr int MF   = WTM / 16;       // 4
    constexpr int NF   = WTN / 8;        // 4 or 2
    constexpr int ASTR = (ALAYOUT == 0) ? 20 : (BM + 8);
    constexpr int ASZ  = (ALAYOUT == 0) ? BM * 20 : BK * (BM + 8);
    constexpr int BSTR = BN + 8;
    constexpr int ANV  = (BM * BK) / (256 * 4);   // float4 per thread (A)
    constexpr int BNV  = (BN * BK) / (256 * 4);   // float4 per thread (B)
    constexpr int AMQ4 = BM / 4;
    constexpr int BNQ4 = BN / 4;

    __shared__ __align__(16) float As[2][ASZ];
    __shared__ __align__(16) float Bs[2][BK * BSTR];

    int z = blockIdx.z;
    int zn = z / zH, zh = z - zn * zH;
    A += (size_t)zn * aZn + (size_t)zh * aZh;
    B += (size_t)zn * bZn + (size_t)zh * bZh;
    C += (size_t)zn * cZn + (size_t)zh * cZh;
    const float* mx = nullptr; const float* isum = nullptr;
    if (SOFTB) {
        const float* sb = sst + (size_t)zn * sZn + (size_t)zh * sZh;
        mx = sb; isum = sb + VOX;
    }
    if (HAS_BIAS) bias += (size_t)zn * biasZn;
    if (HAS_RES)  res  += (size_t)zn * rZn + (size_t)zh * rZh;

    int m0 = blockIdx.x * BM;
    int n0 = blockIdx.y * BN;
    int tid = threadIdx.x;
    int lane = tid & 31, warp = tid >> 5;
    int wm = warp / WN, wn = warp % WN;
    int mbase = wm * WTM, nbase = wn * WTN;

    float acc[MF][NF][4];
    #pragma unroll
    for (int i = 0; i < MF; i++)
        #pragma unroll
        for (int j = 0; j < NF; j++)
            #pragma unroll
            for (int r = 0; r < 4; r++) acc[i][j][r] = 0.f;

    float4 ar[ANV], br[BNV];
    float4 mxr[BNV], isr[BNV];
    if (SOFTB) {
        #pragma unroll
        for (int l = 0; l < BNV; l++) {
            int idx = l * 256 + tid;
            int nq = idx % BNQ4;
            mxr[l] = *(const float4*)(mx   + n0 + nq * 4);
            isr[l] = *(const float4*)(isum + n0 + nq * 4);
        }
    }

    auto loadA = [&](int k0) {
        #pragma unroll
        for (int l = 0; l < ANV; l++) {
            int idx = l * 256 + tid;
            if (ALAYOUT == 0) {
                int m = idx >> 2, kq = idx & 3;
                ar[l] = *(const float4*)(A + (size_t)(m0 + m) * lda + k0 + kq * 4);
            } else {
                int mq = idx % AMQ4, k = idx / AMQ4;
                ar[l] = *(const float4*)(A + (size_t)(k0 + k) * lda + m0 + mq * 4);
            }
        }
    };
    auto loadB = [&](int k0) {
        #pragma unroll
        for (int l = 0; l < BNV; l++) {
            int idx = l * 256 + tid;
            int nq = idx % BNQ4, k = idx / BNQ4;
            br[l] = *(const float4*)(B + (size_t)(k0 + k) * ldb + n0 + nq * 4);
        }
    };
    auto stsA = [&](int buf) {
        #pragma unroll
        for (int l = 0; l < ANV; l++) {
            int idx = l * 256 + tid;
            float4 o;
            o.x = __uint_as_float(f2tf(ar[l].x));
            o.y = __uint_as_float(f2tf(ar[l].y));
            o.z = __uint_as_float(f2tf(ar[l].z));
            o.w = __uint_as_float(f2tf(ar[l].w));
            if (ALAYOUT == 0) {
                int m = idx >> 2, kq = idx & 3;
                *(float4*)&As[buf][m * 20 + kq * 4] = o;
            } else {
                int mq = idx % AMQ4, k = idx / AMQ4;
                *(float4*)&As[buf][k * (BM + 8) + mq * 4] = o;
            }
        }
    };
    auto stsB = [&](int buf) {
        #pragma unroll
        for (int l = 0; l < BNV; l++) {
            int idx = l * 256 + tid;
            int nq = idx % BNQ4, k = idx / BNQ4;
            float4 v = br[l];
            if (SOFTB) {
                v.x = __expf(v.x - mxr[l].x) * isr[l].x;
                v.y = __expf(v.y - mxr[l].y) * isr[l].y;
                v.z = __expf(v.z - mxr[l].z) * isr[l].z;
                v.w = __expf(v.w - mxr[l].w) * isr[l].w;
            }
            float4 o;
            o.x = __uint_as_float(f2tf(v.x));
            o.y = __uint_as_float(f2tf(v.y));
            o.z = __uint_as_float(f2tf(v.z));
            o.w = __uint_as_float(f2tf(v.w));
            *(float4*)&Bs[buf][k * BSTR + nq * 4] = o;
        }
    };

    int NIT = K / BK;
    loadA(0); loadB(0);
    stsA(0);  stsB(0);
    __syncthreads();

    for (int it = 0; it < NIT; it++) {
        int buf = it & 1;
        if (it + 1 < NIT) { loadA((it + 1) * BK); loadB((it + 1) * BK); }
        // compute from buf
        #pragma unroll
        for (int kk = 0; kk < 2; kk++) {
            uint32_t af[MF][4], bf[NF][2];
            int c0 = kk * 8 + (lane & 3);
            int r0 = (lane >> 2);
            #pragma unroll
            for (int mi = 0; mi < MF; mi++) {
                int r = mbase + mi * 16 + r0;
                if (ALAYOUT == 0) {
                    af[mi][0] = __float_as_uint(As[buf][r * 20 + c0]);
                    af[mi][1] = __float_as_uint(As[buf][(r + 8) * 20 + c0]);
                    af[mi][2] = __float_as_uint(As[buf][r * 20 + c0 + 4]);
                    af[mi][3] = __float_as_uint(As[buf][(r + 8) * 20 + c0 + 4]);
                } else {
                    af[mi][0] = __float_as_uint(As[buf][c0 * (BM + 8) + r]);
                    af[mi][1] = __float_as_uint(As[buf][c0 * (BM + 8) + r + 8]);
                    af[mi][2] = __float_as_uint(As[buf][(c0 + 4) * (BM + 8) + r]);
                    af[mi][3] = __float_as_uint(As[buf][(c0 + 4) * (BM + 8) + r + 8]);
                }
            }
            #pragma unroll
            for (int ni = 0; ni < NF; ni++) {
                int cn = nbase + ni * 8 + r0;
                bf[ni][0] = __float_as_uint(Bs[buf][c0 * BSTR + cn]);
                bf[ni][1] = __float_as_uint(Bs[buf][(c0 + 4) * BSTR + cn]);
            }
            #pragma unroll
            for (int mi = 0; mi < MF; mi++)
                #pragma unroll
                for (int ni = 0; ni < NF; ni++)
                    mma8(acc[mi][ni], af[mi], bf[ni]);
        }
        if (it + 1 < NIT) { stsA(buf ^ 1); stsB(buf ^ 1); }
        __syncthreads();
    }

    // epilogue
    #pragma unroll
    for (int mi = 0; mi < MF; mi++) {
        int rg0 = m0 + mbase + mi * 16 + (lane >> 2);
        int rg1 = rg0 + 8;
        float bv0 = HAS_BIAS ? bias[rg0] : 0.f;
        float bv1 = HAS_BIAS ? bias[rg1] : 0.f;
        #pragma unroll
        for (int ni = 0; ni < NF; ni++) {
            int cg = n0 + nbase + ni * 8 + 2 * (lane & 3);
            float2 o0, o1;
            o0.x = alpha * (acc[mi][ni][0] + bv0);
            o0.y = alpha * (acc[mi][ni][1] + bv0);
            o1.x = alpha * (acc[mi][ni][2] + bv1);
            o1.y = alpha * (acc[mi][ni][3] + bv1);
            if (HAS_RES) {
                float2 r0v = *(const float2*)&res[(size_t)rg0 * ldc + cg];
                float2 r1v = *(const float2*)&res[(size_t)rg1 * ldc + cg];
                o0.x += r0v.x; o0.y += r0v.y;
                o1.x += r1v.x; o1.y += r1v.y;
            }
            *(float2*)&C[(size_t)rg0 * ldc + cg] = o0;
            *(float2*)&C[(size_t)rg1 * ldc + cg] = o1;
        }
    }
}

// ---------------- local windowed attention (64 tokens, 64 dims) ----------------
__global__ void __launch_bounds__(64) local_attn_k(
    const float* __restrict__ qkv, const float* __restrict__ x, float* __restrict__ y)
{
    int w = blockIdx.x;
    int h = blockIdx.y, n = blockIdx.z;
    int gh = w >> 6, gw = (w >> 3) & 7, gd = w & 7;
    int vbase = gh * 4 * 1024 + gw * 4 * 32 + gd * 4;
    int tid = threadIdx.x;
    int a = tid >> 4, b = (tid >> 2) & 3, c = tid & 3;
    int voff = vbase + a * 1024 + b * 32 + c;

    const float* qb = qkv + ((size_t)n * OQKV + h * HEADD) * VOX;
    const float* kb = qb + (size_t)CCH * VOX;
    const float* vb = qb + (size_t)2 * CCH * VOX;

    __shared__ __align__(16) float kv_sm[64][68];
    __shared__ __align__(16) float qp[64][64];
    const float inv16 = 1.0f / 16.0f;

    for (int i = 0; i < 64; i++) {
        qp[i][tid]    = qb[(size_t)i * VOX + voff] * inv16;
        kv_sm[i][tid] = kb[(size_t)i * VOX + voff];
    }
    __syncthreads();

    float s[64];
    #pragma unroll
    for (int j = 0; j < 64; j++) s[j] = 0.f;
    for (int d = 0; d < 64; d++) {
        float qv = qp[d][tid];
        #pragma unroll
        for (int j4 = 0; j4 < 64; j4 += 4) {
            float4 kk = *(const float4*)&kv_sm[d][j4];
            s[j4+0] += qv * kk.x; s[j4+1] += qv * kk.y;
            s[j4+2] += qv * kk.z; s[j4+3] += qv * kk.w;
        }
    }
    float m = s[0];
    #pragma unroll
    for (int j = 1; j < 64; j++) m = fmaxf(m, s[j]);
    float sum = 0.f;
    #pragma unroll
    for (int j = 0; j < 64; j++) { s[j] = __expf(s[j] - m); sum += s[j]; }
    float inv = 1.0f / sum;
    __syncthreads();

    #pragma unroll
    for (int j = 0; j < 64; j++) qp[j][tid] = s[j] * inv;
    for (int i = 0; i < 64; i++)
        kv_sm[tid][i] = vb[(size_t)i * VOX + voff];
    __syncthreads();

    float out[64];
    #pragma unroll
    for (int d = 0; d < 64; d++) out[d] = 0.f;
    for (int j = 0; j < 64; j++) {
        float pv = qp[j][tid];
        #pragma unroll
        for (int d4 = 0; d4 < 64; d4 += 4) {
            float4 vv = *(const float4*)&kv_sm[j][d4];
            out[d4+0] += pv * vv.x; out[d4+1] += pv * vv.y;
            out[d4+2] += pv * vv.z; out[d4+3] += pv * vv.w;
        }
    }
    const float* xb = x + ((size_t)n * CCH + h * HEADD) * VOX;
    float*       yb = y + ((size_t)n * CCH + h * HEADD) * VOX;
    for (int d = 0; d < 64; d++) {
        size_t idx = (size_t)d * VOX + voff;
        yb[idx] = xb[idx] + out[d];
    }
}

// ---------------- apply groupnorm elementwise ----------------
__global__ void gn_apply_k(const float* __restrict__ y, const float* __restrict__ stats,
                           const float* __restrict__ wgt, const float* __restrict__ bias,
                           float* __restrict__ out) {
    size_t idx = ((size_t)blockIdx.x * 256 + threadIdx.x) * 4;
    int c = (int)((idx >> 15) & 255);
    int n = (int)(idx >> 23);
    float mean = stats[n * 2], r = stats[n * 2 + 1];
    float w = wgt[c] * r;
    float b = bias[c] - mean * w;
    float4 v = *(const float4*)(y + idx);
    v.x = v.x * w + b; v.y = v.y * w + b; v.z = v.z * w + b; v.w = v.w * w + b;
    *(float4*)(out + idx) = v;
}

// ---------------- 4x4x4 average pool ----------------
__global__ void pool_k(const float* __restrict__ ax, float* __restrict__ pooled) {
    int idx = blockIdx.x * 256 + threadIdx.x;
    int pp = idx & 511;
    int c  = (idx >> 9) & 255;
    int n  = idx >> 17;
    int ph = pp >> 6, pw = (pp >> 3) & 7, pd = pp & 7;
    const float* b = ax + ((size_t)n * CCH + c) * VOX + ph * 4 * 1024 + pw * 4 * 32 + pd * 4;
    float s = 0.f;
    #pragma unroll
    for (int a = 0; a < 4; a++)
        #pragma unroll
        for (int bb = 0; bb < 4; bb++) {
            float4 v = *(const float4*)&b[a * 1024 + bb * 32];
            s += v.x + v.y + v.z + v.w;
        }
    pooled[idx] = s * (1.0f / 64.0f);
}

// ---------------- column softmax stats over S[p][v] ----------------
__global__ void softstats_k(const float* __restrict__ S, float* __restrict__ sst) {
    int v = blockIdx.x * 256 + threadIdx.x;
    int z = blockIdx.y;
    const float* col = S + (size_t)z * PPOOL * VOX + v;
    float m = -1e30f, s = 0.f;
    for (int p = 0; p < PPOOL; p++) {
        float val = col[(size_t)p * VOX];
        if (val > m) { s = s * __expf(m - val) + 1.f; m = val; }
        else         { s += __expf(val - m); }
    }
    float* o = sst + (size_t)z * 2 * VOX;
    o[v] = m; o[VOX + v] = 1.0f / s;
}

// ---------------- launch ----------------
extern "C" void kernel_launch(void* const* d_in, const int* in_sizes, int n_in,
                              void* d_out, int out_size) {
    const float* x       = (const float*)d_in[0];
    const float* qkv_w   = (const float*)d_in[1];
    const float* qkv_b   = (const float*)d_in[2];
    const float* norm_w  = (const float*)d_in[3];
    const float* norm_b  = (const float*)d_in[4];
    const float* anw     = (const float*)d_in[5];
    const float* anb     = (const float*)d_in[6];
    const float* dsw     = (const float*)d_in[7];
    const float* dsb     = (const float*)d_in[8];
    const float* q_w     = (const float*)d_in[9];
    const float* q_b     = (const float*)d_in[10];
    const float* kv_w    = (const float*)d_in[11];
    const float* kv_b    = (const float*)d_in[12];
    const float* proj_w  = (const float*)d_in[13];
    const float* proj_b  = (const float*)d_in[14];
    float* out = (float*)d_out;

    float *W1, *B1, *W3, *B3, *qkv, *y, *attnx, *pooled, *kv2, *q2, *S, *sst, *g;
    float *st1, *st2, *st3;
    double* part;
    cudaGetSymbolAddress((void**)&W1, d_W1);
    cudaGetSymbolAddress((void**)&B1, d_B1);
    cudaGetSymbolAddress((void**)&W3, d_W3);
    cudaGetSymbolAddress((void**)&B3, d_B3);
    cudaGetSymbolAddress((void**)&qkv, d_qkv);
    cudaGetSymbolAddress((void**)&y, d_y);
    cudaGetSymbolAddress((void**)&attnx, d_attnx);
    cudaGetSymbolAddress((void**)&pooled, d_pooled);
    cudaGetSymbolAddress((void**)&kv2, d_kv2);
    cudaGetSymbolAddress((void**)&q2, d_q2);
    cudaGetSymbolAddress((void**)&S, d_S);
    cudaGetSymbolAddress((void**)&sst, d_sst);
    cudaGetSymbolAddress((void**)&g, d_g);
    cudaGetSymbolAddress((void**)&part, d_part);
    cudaGetSymbolAddress((void**)&st1, d_stats1);
    cudaGetSymbolAddress((void**)&st2, d_stats2);
    cudaGetSymbolAddress((void**)&st3, d_stats3);

    const long CV = (long)CCH * VOX;

    // 1) stats over x, fold into qkv conv
    redsum_k<<<dim3(256, NSAMP), 256>>>(x, CV, 256, part);
    redfin_k<<<NSAMP, 256>>>(part, 256, CV, st1);
    buildW_k<<<(NSAMP * OQKV * CCH + 255) / 256, 256>>>(qkv_w, norm_w, st1, W1, OQKV);
    buildB_k<<<(NSAMP * OQKV * 32 + 255) / 256, 256>>>(qkv_w, norm_w, norm_b, qkv_b, st1, B1, OQKV);

    // 2) qkv = W1 @ x + B1   (M=768, N=32768, K=256, z=2)
    tgemm_k<128,128,2,4, 0,1,0,0><<<dim3(OQKV/128, VOX/128, NSAMP), 256>>>(
        W1, (long)OQKV*CCH, 0, CCH,  x, CV, 0, VOX,
        qkv, (long)OQKV*VOX, 0, VOX, CCH, 1,
        B1, OQKV, nullptr, 0, 0, nullptr, 0, 0, 1.0f);

    // 3) local attention -> y = x + attn
    local_attn_k<<<dim3(512, NHEAD, NSAMP), 64>>>(qkv, x, y);

    // 4) attn groupnorm
    redsum_k<<<dim3(256, NSAMP), 256>>>(y, CV, 256, part);
    redfin_k<<<NSAMP, 256>>>(part, 256, CV, st2);
    gn_apply_k<<<(int)(NSAMP * CV / 4 / 256), 256>>>(y, st2, anw, anb, attnx);

    // 5) pool + ds groupnorm folded into kv conv
    pool_k<<<NSAMP * CCH * PPOOL / 256, 256>>>(attnx, pooled);
    redsum_k<<<dim3(8, NSAMP), 256>>>(pooled, (long)CCH * PPOOL, 8, part);
    redfin_k<<<NSAMP, 256>>>(part, 8, (long)CCH * PPOOL, st3);
    buildW_k<<<(NSAMP * OKV * CCH + 255) / 256, 256>>>(kv_w, dsw, st3, W3, OKV);
    buildB_k<<<(NSAMP * OKV * 32 + 255) / 256, 256>>>(kv_w, dsw, dsb, kv_b, st3, B3, OKV);

    // 6) kv2 = W3 @ pooled + B3   (M=512, N=512, K=256, z=2)
    tgemm_k<128,128,2,4, 0,1,0,0><<<dim3(OKV/128, PPOOL/128, NSAMP), 256>>>(
        W3, (long)OKV*CCH, 0, CCH,  pooled, (long)CCH*PPOOL, 0, PPOOL,
        kv2, (long)OKV*PPOOL, 0, PPOOL, CCH, 1,
        B3, OKV, nullptr, 0, 0, nullptr, 0, 0, 1.0f);

    // 7) q2 = (q_w @ attnx + q_b) / 16   (M=256, N=32768, K=256, z=2)
    tgemm_k<128,128,2,4, 0,1,0,0><<<dim3(CCH/128, VOX/128, NSAMP), 256>>>(
        q_w, 0, 0, CCH,  attnx, CV, 0, VOX,
        q2, CV, 0, VOX, CCH, 1,
        q_b, 0, nullptr, 0, 0, nullptr, 0, 0, 1.0f/16.0f);

    // 8) S[p][v] GEMM  (M=512, N=32768, K=64, z=8; A = k2 stored [K][M])
    tgemm_k<128,128,2,4, 1,0,0,0><<<dim3(PPOOL/128, VOX/128, NSAMP*NHEAD), 256>>>(
        kv2, (long)OKV*PPOOL, (long)HEADD*PPOOL, PPOOL,
        q2, CV, (long)HEADD*VOX, VOX,
        S, (long)NHEAD*PPOOL*VOX, (long)PPOOL*VOX, VOX,
        HEADD, NHEAD,
        nullptr, 0, nullptr, 0, 0, nullptr, 0, 0, 1.0f);

    // 9) softmax stats per column
    softstats_k<<<dim3(VOX/256, NSAMP*NHEAD), 256>>>(S, sst);

    // 10) g = v2 @ softmax(S) + attnx   (M=64, N=32768, K=512, z=8)
    tgemm_k<64,128,1,8, 0,0,1,1><<<dim3(1, VOX/128, NSAMP*NHEAD), 256>>>(
        kv2 + CCH * PPOOL, (long)OKV*PPOOL, (long)HEADD*PPOOL, PPOOL,
        S, (long)NHEAD*PPOOL*VOX, (long)PPOOL*VOX, VOX,
        g, CV, (long)HEADD*VOX, VOX,
        PPOOL, NHEAD,
        nullptr, 0,
        attnx, CV, (long)HEADD*VOX,
        sst, (long)NHEAD*2*VOX, (long)2*VOX, 1.0f);

    // 11) out = proj_w @ g + proj_b   (M=256, N=32768, K=256, z=2)
    tgemm_k<128,128,2,4, 0,1,0,0><<<dim3(CCH/128, VOX/128, NSAMP), 256>>>(
        proj_w, 0, 0, CCH,  g, CV, 0, VOX,
        out, CV, 0, VOX, CCH, 1,
        proj_b, 0, nullptr, 0, 0, nullptr, 0, 0, 1.0f);
}